// round 1
// baseline (speedup 1.0000x reference)
#include <cuda_runtime.h>
#include <cstdint>

// WindowAttention: B=4096 windows, N=64 tokens, C=128 dim, fp32 in/out.
// One CTA per window, 128 threads (4 warps, each owning a 16-row stripe).
// All GEMMs via mma.sync.m16n8k8 tf32 with fp32 accumulate.

#define NTOK 64
#define CDIM 128

// smem pitches (floats) chosen for conflict-free / low-conflict LDS
#define PX 132   // Xs, Qs, Ks pitch
#define PV 136   // Vs pitch (B-operand of PV gemm: (t*136+g)%32 -> (8t+g), conflict-free)
#define PS 68    // Ss (softmax probs) pitch
#define PW 72    // Wt weight tile pitch ((t*72+g)%32 -> (8t+g), conflict-free)

#define SMEM_FLOATS (3*64*PX + 64*PV + 64*PS + 128*PW)
#define SMEM_BYTES  (SMEM_FLOATS * 4)

__device__ __forceinline__ float tf32f(float x) {
    uint32_t u;
    asm("cvt.rna.tf32.f32 %0, %1;" : "=r"(u) : "f"(x));
    return __uint_as_float(u);
}

__device__ __forceinline__ void mma8(float acc[4],
                                     uint32_t a0, uint32_t a1, uint32_t a2, uint32_t a3,
                                     uint32_t b0, uint32_t b1) {
    asm volatile(
        "mma.sync.aligned.m16n8k8.row.col.f32.tf32.tf32.f32 "
        "{%0,%1,%2,%3}, {%4,%5,%6,%7}, {%8,%9}, {%0,%1,%2,%3};\n"
        : "+f"(acc[0]), "+f"(acc[1]), "+f"(acc[2]), "+f"(acc[3])
        : "r"(a0), "r"(a1), "r"(a2), "r"(a3), "r"(b0), "r"(b1));
}

__global__ void __launch_bounds__(128, 1)
win_attn_kernel(const float* __restrict__ x,
                const float* __restrict__ wqkv,
                const float* __restrict__ bqkv,
                const float* __restrict__ wproj,
                const float* __restrict__ bproj,
                float* __restrict__ out)
{
    extern __shared__ float smem[];
    float* Xs = smem;                 // [64][PX]
    float* Qs = Xs + 64 * PX;         // [64][PX]  (later reused for O)
    float* Ks = Qs + 64 * PX;         // [64][PX]
    float* Vs = Ks + 64 * PX;         // [64][PV]
    float* Ss = Vs + 64 * PV;         // [64][PS]
    float* Wt = Ss + 64 * PS;         // [128][PW]

    const int tid  = threadIdx.x;
    const int warp = tid >> 5;
    const int lane = tid & 31;
    const int g    = lane >> 2;   // groupID (row within m16 tile)
    const int t    = lane & 3;    // threadID_in_group
    const int mrow = warp * 16;   // this warp's 16-row stripe

    const float* xw = x + (size_t)blockIdx.x * NTOK * CDIM;

    // ---- load X tile [64][128] -> smem (tf32-rounded) ----
    for (int i = tid; i < NTOK * 32; i += 128) {
        int r  = i >> 5;
        int c4 = (i & 31) << 2;
        float4 v = *(const float4*)(xw + r * CDIM + c4);
        float* d = Xs + r * PX + c4;
        d[0] = tf32f(v.x); d[1] = tf32f(v.y); d[2] = tf32f(v.z); d[3] = tf32f(v.w);
    }
    __syncthreads();

    // ================= GEMM1: QKV = X @ Wqkv + b  (6 chunks of 64 cols) =================
    for (int chunk = 0; chunk < 6; ++chunk) {
        const int j0 = chunk * 64;
        // cooperative load of weight tile [128][64] into Wt
        for (int i = tid; i < 128 * 16; i += 128) {
            int r  = i >> 4;
            int c4 = (i & 15) << 2;
            float4 v = *(const float4*)(wqkv + r * 384 + j0 + c4);
            float* d = Wt + r * PW + c4;
            d[0] = tf32f(v.x); d[1] = tf32f(v.y); d[2] = tf32f(v.z); d[3] = tf32f(v.w);
        }
        __syncthreads();

        float acc[8][4];
        #pragma unroll
        for (int i = 0; i < 8; ++i)
            acc[i][0] = acc[i][1] = acc[i][2] = acc[i][3] = 0.f;

        #pragma unroll
        for (int k0 = 0; k0 < 128; k0 += 8) {
            const float* xr = Xs + (mrow + g) * PX + k0 + t;
            uint32_t a0 = __float_as_uint(xr[0]);
            uint32_t a2 = __float_as_uint(xr[4]);
            uint32_t a1 = __float_as_uint(xr[8 * PX]);
            uint32_t a3 = __float_as_uint(xr[8 * PX + 4]);
            const float* wr = Wt + (k0 + t) * PW + g;
            #pragma unroll
            for (int nt = 0; nt < 8; ++nt) {
                uint32_t b0 = __float_as_uint(wr[nt * 8]);
                uint32_t b1 = __float_as_uint(wr[4 * PW + nt * 8]);
                mma8(acc[nt], a0, a1, a2, a3, b0, b1);
            }
        }

        // epilogue: +bias, tf32-round, scatter to Q/K/V smem
        float* dst; int pad; int jb;
        if (chunk < 2)      { dst = Qs; pad = PX; jb = j0; }
        else if (chunk < 4) { dst = Ks; pad = PX; jb = j0 - 128; }
        else                { dst = Vs; pad = PV; jb = j0 - 256; }
        #pragma unroll
        for (int nt = 0; nt < 8; ++nt) {
            int j  = j0 + nt * 8 + 2 * t;
            int jl = jb + nt * 8 + 2 * t;
            float bv0 = __ldg(bqkv + j);
            float bv1 = __ldg(bqkv + j + 1);
            dst[(mrow + g) * pad + jl]         = tf32f(acc[nt][0] + bv0);
            dst[(mrow + g) * pad + jl + 1]     = tf32f(acc[nt][1] + bv1);
            dst[(mrow + g + 8) * pad + jl]     = tf32f(acc[nt][2] + bv0);
            dst[(mrow + g + 8) * pad + jl + 1] = tf32f(acc[nt][3] + bv1);
        }
        __syncthreads();
    }

    // ================= GEMM2: S = Q @ K^T  (each warp: 16 rows x 64 cols) =================
    float sacc[8][4];
    #pragma unroll
    for (int i = 0; i < 8; ++i)
        sacc[i][0] = sacc[i][1] = sacc[i][2] = sacc[i][3] = 0.f;

    #pragma unroll
    for (int k0 = 0; k0 < 128; k0 += 8) {
        const float* qr = Qs + (mrow + g) * PX + k0 + t;
        uint32_t a0 = __float_as_uint(qr[0]);
        uint32_t a2 = __float_as_uint(qr[4]);
        uint32_t a1 = __float_as_uint(qr[8 * PX]);
        uint32_t a3 = __float_as_uint(qr[8 * PX + 4]);
        #pragma unroll
        for (int nt = 0; nt < 8; ++nt) {
            const float* kr = Ks + (nt * 8 + g) * PX + k0 + t;
            uint32_t b0 = __float_as_uint(kr[0]);
            uint32_t b1 = __float_as_uint(kr[4]);
            mma8(sacc[nt], a0, a1, a2, a3, b0, b1);
        }
    }

    // ---- softmax (rows are warp-local: 2 rows per thread across quad) ----
    const float scale = 0.08838834764831844f;  // 128^-0.5
    float mx0 = -1e30f, mx1 = -1e30f;
    #pragma unroll
    for (int nt = 0; nt < 8; ++nt) {
        sacc[nt][0] *= scale; sacc[nt][1] *= scale;
        sacc[nt][2] *= scale; sacc[nt][3] *= scale;
        mx0 = fmaxf(mx0, fmaxf(sacc[nt][0], sacc[nt][1]));
        mx1 = fmaxf(mx1, fmaxf(sacc[nt][2], sacc[nt][3]));
    }
    mx0 = fmaxf(mx0, __shfl_xor_sync(0xffffffffu, mx0, 1));
    mx0 = fmaxf(mx0, __shfl_xor_sync(0xffffffffu, mx0, 2));
    mx1 = fmaxf(mx1, __shfl_xor_sync(0xffffffffu, mx1, 1));
    mx1 = fmaxf(mx1, __shfl_xor_sync(0xffffffffu, mx1, 2));

    float s0 = 0.f, s1 = 0.f;
    #pragma unroll
    for (int nt = 0; nt < 8; ++nt) {
        float p0 = __expf(sacc[nt][0] - mx0);
        float p1 = __expf(sacc[nt][1] - mx0);
        float p2 = __expf(sacc[nt][2] - mx1);
        float p3 = __expf(sacc[nt][3] - mx1);
        sacc[nt][0] = p0; sacc[nt][1] = p1; sacc[nt][2] = p2; sacc[nt][3] = p3;
        s0 += p0 + p1; s1 += p2 + p3;
    }
    s0 += __shfl_xor_sync(0xffffffffu, s0, 1);
    s0 += __shfl_xor_sync(0xffffffffu, s0, 2);
    s1 += __shfl_xor_sync(0xffffffffu, s1, 1);
    s1 += __shfl_xor_sync(0xffffffffu, s1, 2);
    float r0 = 1.f / s0, r1 = 1.f / s1;

    #pragma unroll
    for (int nt = 0; nt < 8; ++nt) {
        int j = nt * 8 + 2 * t;
        Ss[(mrow + g) * PS + j]         = tf32f(sacc[nt][0] * r0);
        Ss[(mrow + g) * PS + j + 1]     = tf32f(sacc[nt][1] * r0);
        Ss[(mrow + g + 8) * PS + j]     = tf32f(sacc[nt][2] * r1);
        Ss[(mrow + g + 8) * PS + j + 1] = tf32f(sacc[nt][3] * r1);
    }
    // No __syncthreads needed: each warp only reads its own Ss rows below,
    // and only its own Qs rows are overwritten by its own O stripe.

    // ================= GEMM3: O = P @ V  (16 rows x 128 cols per warp) =================
    float oacc[16][4];
    #pragma unroll
    for (int i = 0; i < 16; ++i)
        oacc[i][0] = oacc[i][1] = oacc[i][2] = oacc[i][3] = 0.f;

    #pragma unroll
    for (int k0 = 0; k0 < 64; k0 += 8) {
        const float* pr = Ss + (mrow + g) * PS + k0 + t;
        uint32_t a0 = __float_as_uint(pr[0]);
        uint32_t a2 = __float_as_uint(pr[4]);
        uint32_t a1 = __float_as_uint(pr[8 * PS]);
        uint32_t a3 = __float_as_uint(pr[8 * PS + 4]);
        const float* vr = Vs + (k0 + t) * PV + g;
        #pragma unroll
        for (int nt = 0; nt < 16; ++nt) {
            uint32_t b0 = __float_as_uint(vr[nt * 8]);
            uint32_t b1 = __float_as_uint(vr[4 * PV + nt * 8]);
            mma8(oacc[nt], a0, a1, a2, a3, b0, b1);
        }
    }

    // store O into this warp's own Qs rows (Q no longer needed)
    #pragma unroll
    for (int nt = 0; nt < 16; ++nt) {
        int j = nt * 8 + 2 * t;
        Qs[(mrow + g) * PX + j]         = tf32f(oacc[nt][0]);
        Qs[(mrow + g) * PX + j + 1]     = tf32f(oacc[nt][1]);
        Qs[(mrow + g + 8) * PX + j]     = tf32f(oacc[nt][2]);
        Qs[(mrow + g + 8) * PX + j + 1] = tf32f(oacc[nt][3]);
    }

    // ================= GEMM4: out = O @ Wproj + b  (2 chunks of 64 cols) =================
    float* outw = out + (size_t)blockIdx.x * NTOK * CDIM;
    for (int chunk = 0; chunk < 2; ++chunk) {
        const int j0 = chunk * 64;
        __syncthreads();  // all warps done with previous Wt contents
        for (int i = tid; i < 128 * 16; i += 128) {
            int r  = i >> 4;
            int c4 = (i & 15) << 2;
            float4 v = *(const float4*)(wproj + r * 128 + j0 + c4);
            float* d = Wt + r * PW + c4;
            d[0] = tf32f(v.x); d[1] = tf32f(v.y); d[2] = tf32f(v.z); d[3] = tf32f(v.w);
        }
        __syncthreads();

        float acc[8][4];
        #pragma unroll
        for (int i = 0; i < 8; ++i)
            acc[i][0] = acc[i][1] = acc[i][2] = acc[i][3] = 0.f;

        #pragma unroll
        for (int k0 = 0; k0 < 128; k0 += 8) {
            const float* orow = Qs + (mrow + g) * PX + k0 + t;
            uint32_t a0 = __float_as_uint(orow[0]);
            uint32_t a2 = __float_as_uint(orow[4]);
            uint32_t a1 = __float_as_uint(orow[8 * PX]);
            uint32_t a3 = __float_as_uint(orow[8 * PX + 4]);
            const float* wr = Wt + (k0 + t) * PW + g;
            #pragma unroll
            for (int nt = 0; nt < 8; ++nt) {
                uint32_t b0 = __float_as_uint(wr[nt * 8]);
                uint32_t b1 = __float_as_uint(wr[4 * PW + nt * 8]);
                mma8(acc[nt], a0, a1, a2, a3, b0, b1);
            }
        }

        #pragma unroll
        for (int nt = 0; nt < 8; ++nt) {
            int j = j0 + nt * 8 + 2 * t;
            float bv0 = __ldg(bproj + j);
            float bv1 = __ldg(bproj + j + 1);
            float2 v0 = make_float2(acc[nt][0] + bv0, acc[nt][1] + bv1);
            float2 v1 = make_float2(acc[nt][2] + bv0, acc[nt][3] + bv1);
            *(float2*)(outw + (mrow + g) * CDIM + j)     = v0;
            *(float2*)(outw + (mrow + g + 8) * CDIM + j) = v1;
        }
    }
}

extern "C" void kernel_launch(void* const* d_in, const int* in_sizes, int n_in,
                              void* d_out, int out_size)
{
    const float* x     = (const float*)d_in[0];
    const float* wqkv  = (const float*)d_in[1];
    const float* bqkv  = (const float*)d_in[2];
    const float* wproj = (const float*)d_in[3];
    const float* bproj = (const float*)d_in[4];
    float* out = (float*)d_out;

    const int nwin = in_sizes[0] / (NTOK * CDIM);  // 4096

    cudaFuncSetAttribute(win_attn_kernel,
                         cudaFuncAttributeMaxDynamicSharedMemorySize, SMEM_BYTES);

    win_attn_kernel<<<nwin, 128, SMEM_BYTES>>>(x, wqkv, bqkv, wproj, bproj, out);
}

// round 2
// speedup vs baseline: 1.6922x; 1.6922x over previous
#include <cuda_runtime.h>
#include <cstdint>

// WindowAttention: B=4096 windows, N=64 tokens, C=128 dim, fp32 in/out.
// One CTA per window, 256 threads (8 warps). Warp = (wr, wc):
//   wr = warp&3  -> 16-row stripe,  wc = warp>>2 -> column half.
// All GEMMs via mma.sync.m16n8k8 tf32, fp32 accumulate.
// Weight tiles double-buffered; softmax uses pair barriers (bar.sync wr+1, 64).

#define NTOK 64
#define CDIM 128
#define PX 132   // X/Q/K pitch: bank = 4g+t  (conflict-free A & K-B frags)
#define PV 136   // V pitch:     bank = 8t+g  (conflict-free B frags)
#define PS 68    // S pitch:     bank = 4g+t
#define PW 72    // W pitch:     bank = 8t+g

#define OFF_X  0
#define OFF_Q  (64*PX)
#define OFF_K  (2*64*PX)
#define OFF_V  (3*64*PX)
#define OFF_WA (3*64*PX + 64*PV)
#define OFF_WB (OFF_WA + 128*PW)
#define OFF_S  OFF_WA                // S aliases Wt buffer A (dead in between)
#define OFF_PM (OFF_WA + 64*PS)      // pmax[64][2] then psum[64][2]
#define SMEM_FLOATS (OFF_WB + 128*PW)
#define SMEM_BYTES  (SMEM_FLOATS * 4)   // 209,920 B

__device__ __forceinline__ float tf32f(float x) {
    uint32_t u;
    asm("cvt.rna.tf32.f32 %0, %1;" : "=r"(u) : "f"(x));
    return __uint_as_float(u);
}

__device__ __forceinline__ void mma8(float acc[4],
                                     uint32_t a0, uint32_t a1, uint32_t a2, uint32_t a3,
                                     uint32_t b0, uint32_t b1) {
    asm volatile(
        "mma.sync.aligned.m16n8k8.row.col.f32.tf32.tf32.f32 "
        "{%0,%1,%2,%3}, {%4,%5,%6,%7}, {%8,%9}, {%0,%1,%2,%3};\n"
        : "+f"(acc[0]), "+f"(acc[1]), "+f"(acc[2]), "+f"(acc[3])
        : "r"(a0), "r"(a1), "r"(a2), "r"(a3), "r"(b0), "r"(b1));
}

__device__ __forceinline__ void barpair(int id) {
    asm volatile("bar.sync %0, 64;" :: "r"(id) : "memory");
}

__global__ void __launch_bounds__(256, 1)
win_attn_kernel(const float* __restrict__ x,
                const float* __restrict__ wqkv,
                const float* __restrict__ bqkv,
                const float* __restrict__ wproj,
                const float* __restrict__ bproj,
                float* __restrict__ out)
{
    extern __shared__ float smem[];
    float* Xs = smem + OFF_X;
    float* Qs = smem + OFF_Q;     // later reused for O
    float* Ks = smem + OFF_K;
    float* Vs = smem + OFF_V;
    float* Ss = smem + OFF_S;
    float* Pm = smem + OFF_PM;

    const int tid  = threadIdx.x;
    const int warp = tid >> 5;
    const int lane = tid & 31;
    const int g    = lane >> 2;
    const int t    = lane & 3;
    const int wr   = warp & 3;
    const int wc   = warp >> 2;
    const int mrow = wr * 16;
    const int nbase = wc * 32;

    const float* xw = x + (size_t)blockIdx.x * NTOK * CDIM;

    // ---------- prologue: load X + weight chunk0, stage chunk1 ----------
    float4 xs4[8];
    #pragma unroll
    for (int s = 0; s < 8; ++s) {
        int i = tid + s * 256;
        xs4[s] = *(const float4*)(xw + (i >> 5) * CDIM + ((i & 31) << 2));
    }
    float4 ws4[8];
    #pragma unroll
    for (int s = 0; s < 8; ++s) {
        int i = tid + s * 256;
        ws4[s] = *(const float4*)(wqkv + (i >> 4) * 384 + ((i & 15) << 2));
    }
    #pragma unroll
    for (int s = 0; s < 8; ++s) {
        int i = tid + s * 256;
        float* d = Xs + (i >> 5) * PX + ((i & 31) << 2);
        d[0] = tf32f(xs4[s].x); d[1] = tf32f(xs4[s].y);
        d[2] = tf32f(xs4[s].z); d[3] = tf32f(xs4[s].w);
    }
    #pragma unroll
    for (int s = 0; s < 8; ++s) {
        int i = tid + s * 256;
        float* d = smem + OFF_WA + (i >> 4) * PW + ((i & 15) << 2);
        d[0] = tf32f(ws4[s].x); d[1] = tf32f(ws4[s].y);
        d[2] = tf32f(ws4[s].z); d[3] = tf32f(ws4[s].w);
    }
    #pragma unroll
    for (int s = 0; s < 8; ++s) {        // stage chunk 1
        int i = tid + s * 256;
        ws4[s] = *(const float4*)(wqkv + (i >> 4) * 384 + 64 + ((i & 15) << 2));
    }
    __syncthreads();

    // ================= GEMM1: QKV = X @ Wqkv + b (6 chunks, double-buffered) ===========
    for (int c = 0; c < 6; ++c) {
        const int j0 = c * 64;
        const float* Wt = smem + ((c & 1) ? OFF_WB : OFF_WA);

        float acc[4][4];
        #pragma unroll
        for (int i = 0; i < 4; ++i)
            acc[i][0] = acc[i][1] = acc[i][2] = acc[i][3] = 0.f;

        #pragma unroll
        for (int k0 = 0; k0 < 128; k0 += 8) {
            const float* xr = Xs + (mrow + g) * PX + k0 + t;
            uint32_t a0 = __float_as_uint(xr[0]);
            uint32_t a2 = __float_as_uint(xr[4]);
            uint32_t a1 = __float_as_uint(xr[8 * PX]);
            uint32_t a3 = __float_as_uint(xr[8 * PX + 4]);
            const float* wrp = Wt + (k0 + t) * PW + nbase + g;
            #pragma unroll
            for (int nt = 0; nt < 4; ++nt) {
                uint32_t b0 = __float_as_uint(wrp[nt * 8]);
                uint32_t b1 = __float_as_uint(wrp[4 * PW + nt * 8]);
                mma8(acc[nt], a0, a1, a2, a3, b0, b1);
            }
        }

        // store staged weights (chunk c+1) into the other buffer
        if (c < 5) {
            float* db = smem + (((c + 1) & 1) ? OFF_WB : OFF_WA);
            #pragma unroll
            for (int s = 0; s < 8; ++s) {
                int i = tid + s * 256;
                float* d = db + (i >> 4) * PW + ((i & 15) << 2);
                d[0] = tf32f(ws4[s].x); d[1] = tf32f(ws4[s].y);
                d[2] = tf32f(ws4[s].z); d[3] = tf32f(ws4[s].w);
            }
        }
        // stage chunk c+2
        if (c < 4) {
            #pragma unroll
            for (int s = 0; s < 8; ++s) {
                int i = tid + s * 256;
                ws4[s] = *(const float4*)(wqkv + (i >> 4) * 384 + (c + 2) * 64 + ((i & 15) << 2));
            }
        }

        // epilogue: +bias, tf32-round, scatter to Q/K/V
        float* dst; int pad; int jb;
        if (c < 2)      { dst = Qs; pad = PX; jb = j0; }
        else if (c < 4) { dst = Ks; pad = PX; jb = j0 - 128; }
        else            { dst = Vs; pad = PV; jb = j0 - 256; }
        #pragma unroll
        for (int nt = 0; nt < 4; ++nt) {
            int jg = j0 + nbase + nt * 8 + 2 * t;   // global col (bias index)
            int jl = jb + nbase + nt * 8 + 2 * t;   // local col in Q/K/V
            float bv0 = __ldg(bqkv + jg);
            float bv1 = __ldg(bqkv + jg + 1);
            float2 v0 = make_float2(tf32f(acc[nt][0] + bv0), tf32f(acc[nt][1] + bv1));
            float2 v1 = make_float2(tf32f(acc[nt][2] + bv0), tf32f(acc[nt][3] + bv1));
            *(float2*)&dst[(mrow + g) * pad + jl]     = v0;
            *(float2*)&dst[(mrow + g + 8) * pad + jl] = v1;
        }
        __syncthreads();
    }

    // ================= GEMM2: S = Q @ K^T (16 rows x 32 cols per warp) =================
    float sacc[4][4];
    #pragma unroll
    for (int i = 0; i < 4; ++i)
        sacc[i][0] = sacc[i][1] = sacc[i][2] = sacc[i][3] = 0.f;

    #pragma unroll
    for (int k0 = 0; k0 < 128; k0 += 8) {
        const float* qr = Qs + (mrow + g) * PX + k0 + t;
        uint32_t a0 = __float_as_uint(qr[0]);
        uint32_t a2 = __float_as_uint(qr[4]);
        uint32_t a1 = __float_as_uint(qr[8 * PX]);
        uint32_t a3 = __float_as_uint(qr[8 * PX + 4]);
        #pragma unroll
        for (int nt = 0; nt < 4; ++nt) {
            const float* kr = Ks + (nbase + nt * 8 + g) * PX + k0 + t;
            uint32_t b0 = __float_as_uint(kr[0]);
            uint32_t b1 = __float_as_uint(kr[4]);
            mma8(sacc[nt], a0, a1, a2, a3, b0, b1);
        }
    }

    // ---- softmax across warp pair (wr fixed, wc = 0/1) ----
    const float scale = 0.08838834764831844f;  // 128^-0.5
    const int bid = wr + 1;
    float mx0 = -1e30f, mx1 = -1e30f;
    #pragma unroll
    for (int nt = 0; nt < 4; ++nt) {
        sacc[nt][0] *= scale; sacc[nt][1] *= scale;
        sacc[nt][2] *= scale; sacc[nt][3] *= scale;
        mx0 = fmaxf(mx0, fmaxf(sacc[nt][0], sacc[nt][1]));
        mx1 = fmaxf(mx1, fmaxf(sacc[nt][2], sacc[nt][3]));
    }
    mx0 = fmaxf(mx0, __shfl_xor_sync(0xffffffffu, mx0, 1));
    mx0 = fmaxf(mx0, __shfl_xor_sync(0xffffffffu, mx0, 2));
    mx1 = fmaxf(mx1, __shfl_xor_sync(0xffffffffu, mx1, 1));
    mx1 = fmaxf(mx1, __shfl_xor_sync(0xffffffffu, mx1, 2));
    if (t == 0) {
        Pm[(mrow + g) * 2 + wc]     = mx0;
        Pm[(mrow + g + 8) * 2 + wc] = mx1;
    }
    barpair(bid);
    mx0 = fmaxf(Pm[(mrow + g) * 2],     Pm[(mrow + g) * 2 + 1]);
    mx1 = fmaxf(Pm[(mrow + g + 8) * 2], Pm[(mrow + g + 8) * 2 + 1]);

    float s0 = 0.f, s1 = 0.f;
    #pragma unroll
    for (int nt = 0; nt < 4; ++nt) {
        float p0 = __expf(sacc[nt][0] - mx0);
        float p1 = __expf(sacc[nt][1] - mx0);
        float p2 = __expf(sacc[nt][2] - mx1);
        float p3 = __expf(sacc[nt][3] - mx1);
        sacc[nt][0] = p0; sacc[nt][1] = p1; sacc[nt][2] = p2; sacc[nt][3] = p3;
        s0 += p0 + p1; s1 += p2 + p3;
    }
    s0 += __shfl_xor_sync(0xffffffffu, s0, 1);
    s0 += __shfl_xor_sync(0xffffffffu, s0, 2);
    s1 += __shfl_xor_sync(0xffffffffu, s1, 1);
    s1 += __shfl_xor_sync(0xffffffffu, s1, 2);
    if (t == 0) {
        Pm[128 + (mrow + g) * 2 + wc]     = s0;
        Pm[128 + (mrow + g + 8) * 2 + wc] = s1;
    }
    barpair(bid);
    float r0 = 1.f / (Pm[128 + (mrow + g) * 2]     + Pm[128 + (mrow + g) * 2 + 1]);
    float r1 = 1.f / (Pm[128 + (mrow + g + 8) * 2] + Pm[128 + (mrow + g + 8) * 2 + 1]);

    #pragma unroll
    for (int nt = 0; nt < 4; ++nt) {
        int j = nbase + nt * 8 + 2 * t;
        float2 v0 = make_float2(tf32f(sacc[nt][0] * r0), tf32f(sacc[nt][1] * r0));
        float2 v1 = make_float2(tf32f(sacc[nt][2] * r1), tf32f(sacc[nt][3] * r1));
        *(float2*)&Ss[(mrow + g) * PS + j]     = v0;
        *(float2*)&Ss[(mrow + g + 8) * PS + j] = v1;
    }
    barpair(bid);   // pair sees full S rows before GEMM3

    // ================= GEMM3: O = P @ V (16 rows x 64 cols per warp) =================
    float oacc[8][4];
    #pragma unroll
    for (int i = 0; i < 8; ++i)
        oacc[i][0] = oacc[i][1] = oacc[i][2] = oacc[i][3] = 0.f;

    const int cbase = wc * 64;
    #pragma unroll
    for (int k0 = 0; k0 < 64; k0 += 8) {
        const float* pr = Ss + (mrow + g) * PS + k0 + t;
        uint32_t a0 = __float_as_uint(pr[0]);
        uint32_t a2 = __float_as_uint(pr[4]);
        uint32_t a1 = __float_as_uint(pr[8 * PS]);
        uint32_t a3 = __float_as_uint(pr[8 * PS + 4]);
        const float* vr = Vs + (k0 + t) * PV + cbase + g;
        #pragma unroll
        for (int nt = 0; nt < 8; ++nt) {
            uint32_t b0 = __float_as_uint(vr[nt * 8]);
            uint32_t b1 = __float_as_uint(vr[4 * PV + nt * 8]);
            mma8(oacc[nt], a0, a1, a2, a3, b0, b1);
        }
    }

    // store O into Qs (Q dead after GEMM2)
    #pragma unroll
    for (int nt = 0; nt < 8; ++nt) {
        int j = cbase + nt * 8 + 2 * t;
        float2 v0 = make_float2(tf32f(oacc[nt][0]), tf32f(oacc[nt][1]));
        float2 v1 = make_float2(tf32f(oacc[nt][2]), tf32f(oacc[nt][3]));
        *(float2*)&Qs[(mrow + g) * PX + j]     = v0;
        *(float2*)&Qs[(mrow + g + 8) * PX + j] = v1;
    }
    __syncthreads();

    // ================= GEMM4: out = O @ Wproj + b (2 chunks of 64 cols) ================
    // load wproj: cols 0-63 -> WtA, cols 64-127 -> WtB (S is dead now)
    float4 wa4[8], wb4[8];
    #pragma unroll
    for (int s = 0; s < 8; ++s) {
        int i = tid + s * 256;
        wa4[s] = *(const float4*)(wproj + (i >> 4) * 128 + ((i & 15) << 2));
        wb4[s] = *(const float4*)(wproj + (i >> 4) * 128 + 64 + ((i & 15) << 2));
    }
    #pragma unroll
    for (int s = 0; s < 8; ++s) {
        int i = tid + s * 256;
        float* da = smem + OFF_WA + (i >> 4) * PW + ((i & 15) << 2);
        float* db = smem + OFF_WB + (i >> 4) * PW + ((i & 15) << 2);
        da[0] = tf32f(wa4[s].x); da[1] = tf32f(wa4[s].y);
        da[2] = tf32f(wa4[s].z); da[3] = tf32f(wa4[s].w);
        db[0] = tf32f(wb4[s].x); db[1] = tf32f(wb4[s].y);
        db[2] = tf32f(wb4[s].z); db[3] = tf32f(wb4[s].w);
    }
    __syncthreads();

    float* outw = out + (size_t)blockIdx.x * NTOK * CDIM;
    #pragma unroll
    for (int chunk = 0; chunk < 2; ++chunk) {
        const int j0 = chunk * 64;
        const float* Wt = smem + (chunk ? OFF_WB : OFF_WA);

        float acc[4][4];
        #pragma unroll
        for (int i = 0; i < 4; ++i)
            acc[i][0] = acc[i][1] = acc[i][2] = acc[i][3] = 0.f;

        #pragma unroll
        for (int k0 = 0; k0 < 128; k0 += 8) {
            const float* orow = Qs + (mrow + g) * PX + k0 + t;
            uint32_t a0 = __float_as_uint(orow[0]);
            uint32_t a2 = __float_as_uint(orow[4]);
            uint32_t a1 = __float_as_uint(orow[8 * PX]);
            uint32_t a3 = __float_as_uint(orow[8 * PX + 4]);
            const float* wrp = Wt + (k0 + t) * PW + nbase + g;
            #pragma unroll
            for (int nt = 0; nt < 4; ++nt) {
                uint32_t b0 = __float_as_uint(wrp[nt * 8]);
                uint32_t b1 = __float_as_uint(wrp[4 * PW + nt * 8]);
                mma8(acc[nt], a0, a1, a2, a3, b0, b1);
            }
        }

        #pragma unroll
        for (int nt = 0; nt < 4; ++nt) {
            int j = j0 + nbase + nt * 8 + 2 * t;
            float bv0 = __ldg(bproj + j);
            float bv1 = __ldg(bproj + j + 1);
            float2 v0 = make_float2(acc[nt][0] + bv0, acc[nt][1] + bv1);
            float2 v1 = make_float2(acc[nt][2] + bv0, acc[nt][3] + bv1);
            *(float2*)(outw + (mrow + g) * CDIM + j)     = v0;
            *(float2*)(outw + (mrow + g + 8) * CDIM + j) = v1;
        }
    }
}

extern "C" void kernel_launch(void* const* d_in, const int* in_sizes, int n_in,
                              void* d_out, int out_size)
{
    const float* x     = (const float*)d_in[0];
    const float* wqkv  = (const float*)d_in[1];
    const float* bqkv  = (const float*)d_in[2];
    const float* wproj = (const float*)d_in[3];
    const float* bproj = (const float*)d_in[4];
    float* out = (float*)d_out;

    const int nwin = in_sizes[0] / (NTOK * CDIM);  // 4096

    cudaFuncSetAttribute(win_attn_kernel,
                         cudaFuncAttributeMaxDynamicSharedMemorySize, SMEM_BYTES);

    win_attn_kernel<<<nwin, 256, SMEM_BYTES>>>(x, wqkv, bqkv, wproj, bproj, out);
}